// round 1
// baseline (speedup 1.0000x reference)
#include <cuda_runtime.h>

// HMLoss: 4-region histogram-matching L1 loss, H=W=2048.
// K0: zero accumulators. K1: 24 histograms (shared-mem privatized).
// K2: CDFs + matching tables (12 blocks). K3: L1 residual. K4: finalize.

#define NPIX 4194304   // 2048*2048
#define NQ   1048576   // NPIX/4
#define NB   256
#define NHIST 24       // 4 regions x {src,tar} x 3 channels

__device__ unsigned int g_hist[NHIST * NB];
__device__ float        g_tables[12 * NB];   // [region*3+c][256], stored as float
__device__ double       g_acc;

#define MFACE_S ((1u<<1)|(1u<<7)|(1u<<8)|(1u<<10)|(1u<<11)|(1u<<14))
#define MFACE_T ((1u<<1)|(1u<<7)|(1u<<8)|(1u<<10)|(1u<<14))
#define MHAIR   (1u<<17)
#define MEL     ((1u<<2)|(1u<<4))
#define MER     ((1u<<3)|(1u<<5))

// floor for x in [0, 2^23): round-toward-zero add of 2^23, take mantissa bits.
__device__ __forceinline__ int floor_pos(float x) {
    return __float_as_int(__fadd_rz(x, 8388608.0f)) & 0x7FFFFF;
}

// de_norm: clip((x+1)/2, 0, 1) * 255  -- fma(x,0.5,0.5) rounds identically to (x+1)*0.5
__device__ __forceinline__ float denorm(float x) {
    return __saturatef(fmaf(x, 0.5f, 0.5f)) * 255.0f;
}

// region id from a label-bit; sets are disjoint so select order is irrelevant.
__device__ __forceinline__ int reg_of(unsigned bit, unsigned mface) {
    int r = -1;
    if (bit & MER)   r = 3;
    if (bit & MEL)   r = 2;
    if (bit & MHAIR) r = 1;
    if (bit & mface) r = 0;
    return r;
}

// ---------------------------------------------------------------- K0: zero
__global__ void zero_kernel() {
    int i = blockIdx.x * 256 + threadIdx.x;
    if (i < NHIST * NB) g_hist[i] = 0u;
    if (i == 0) g_acc = 0.0;
}

// ---------------------------------------------------------------- K1: histograms
__device__ __forceinline__ void hist_px(int la, int lb,
                                        float fa, float fb, float fc,
                                        float ra, float rb, float rc,
                                        unsigned int* sh)
{
    const float CB = 256.0f / 255.0f;
    unsigned ab = 1u << la;
    unsigned bb = 1u << lb;

    // ---- src side: histograms of denorm(fake_A) over mask_A regions
    int rs = reg_of(ab, MFACE_S);
    if (rs >= 0) {
        unsigned base = (unsigned)rs * (6 * NB);  // ((rs*2+0)*3+c)*NB
        float v0 = denorm(fa), v1 = denorm(fb), v2 = denorm(fc);
        int b0 = min(floor_pos(v0 * CB), 255);
        int b1 = min(floor_pos(v1 * CB), 255);
        int b2 = min(floor_pos(v2 * CB), 255);
        atomicAdd(&sh[base          + b0], 1u);
        atomicAdd(&sh[base +     NB + b1], 1u);
        atomicAdd(&sh[base + 2 * NB + b2], 1u);
    }

    // ---- tar side: face mask = (mb in faceset) + (ma == 11); value can be 2.
    int rt = reg_of(bb, MFACE_T);
    int faceval = (rt == 0 ? 1 : 0) + (la == 11 ? 1 : 0);
    if (faceval > 0 || rt > 0) {
        // faceval==2 implies rt==0, so one scaled bin serves both targets.
        float scale = (faceval == 2) ? 2.0f : 1.0f;
        float v0 = denorm(ra) * scale, v1 = denorm(rb) * scale, v2 = denorm(rc) * scale;
        int b0 = min(floor_pos(v0 * CB), 255);
        int b1 = min(floor_pos(v1 * CB), 255);
        int b2 = min(floor_pos(v2 * CB), 255);
        if (faceval > 0) {
            unsigned base = 3 * NB;               // region 0, tar
            atomicAdd(&sh[base          + b0], 1u);
            atomicAdd(&sh[base +     NB + b1], 1u);
            atomicAdd(&sh[base + 2 * NB + b2], 1u);
        }
        if (rt > 0) {
            unsigned base = (unsigned)rt * (6 * NB) + 3 * NB;
            atomicAdd(&sh[base          + b0], 1u);
            atomicAdd(&sh[base +     NB + b1], 1u);
            atomicAdd(&sh[base + 2 * NB + b2], 1u);
        }
    }
}

__global__ void __launch_bounds__(512, 2) hist_kernel(
    const float4* __restrict__ fake, const float4* __restrict__ refb,
    const int4* __restrict__ ma, const int4* __restrict__ mb)
{
    __shared__ unsigned int sh[NHIST * NB];
    for (int i = threadIdx.x; i < NHIST * NB; i += 512) sh[i] = 0u;
    __syncthreads();

    int stride = gridDim.x * 512;
    for (int q = blockIdx.x * 512 + threadIdx.x; q < NQ; q += stride) {
        int4   a4 = ma[q],  b4 = mb[q];
        float4 f0 = fake[q], f1 = fake[q + NQ], f2 = fake[q + 2 * NQ];
        float4 r0 = refb[q], r1 = refb[q + NQ], r2 = refb[q + 2 * NQ];
        hist_px(a4.x, b4.x, f0.x, f1.x, f2.x, r0.x, r1.x, r2.x, sh);
        hist_px(a4.y, b4.y, f0.y, f1.y, f2.y, r0.y, r1.y, r2.y, sh);
        hist_px(a4.z, b4.z, f0.z, f1.z, f2.z, r0.z, r1.z, r2.z, sh);
        hist_px(a4.w, b4.w, f0.w, f1.w, f2.w, r0.w, r1.w, r2.w, sh);
    }
    __syncthreads();
    for (int i = threadIdx.x; i < NHIST * NB; i += 512) {
        unsigned v = sh[i];
        if (v) atomicAdd(&g_hist[i], v);
    }
}

// ---------------------------------------------------------------- K2: CDFs + tables
// One block per (region, channel). Sequential cumsum matches reference order.
__global__ void table_kernel()
{
    __shared__ unsigned int cnt[2][NB];
    __shared__ float cd[NB], ca[NB];
    int rc = blockIdx.x;            // 0..11 = region*3 + c
    int region = rc / 3, c = rc % 3;
    int t = threadIdx.x;            // 256 threads

    cnt[0][t] = g_hist[(region * 6 + c)     * NB + t];   // src
    cnt[1][t] = g_hist[(region * 6 + 3 + c) * NB + t];   // tar
    __syncthreads();

    if (t < 2) {
        float tot = 0.0f;
        for (int k = 0; k < NB; k++) tot += (float)cnt[t][k];   // exact (integer < 2^24)
        tot = fmaxf(tot, 1.0f);
        float run = 0.0f;
        float* dst = (t == 0) ? cd : ca;
        for (int k = 0; k < NB; k++) { run += (float)cnt[t][k] / tot; dst[k] = run; }
    }
    __syncthreads();

    // table[i] = first j in 1..255 with ca[j-1] <= cd[i] <= ca[j], else i.
    float dc = cd[t];
    int tbl = t;
    for (int k = 0; k < 255; k++) {
        if (dc >= ca[k] && dc <= ca[k + 1]) { tbl = k + 1; break; }
    }
    if (t == 0)   tbl = 0;
    if (t == 255) tbl = 255;
    g_tables[rc * NB + t] = (float)tbl;
}

// ---------------------------------------------------------------- K3: L1 residual
__device__ __forceinline__ float loss_px(int la, float fa, float fb, float fc,
                                         const float* tbl)
{
    unsigned ab = 1u << la;
    int rs = reg_of(ab, MFACE_S);
    float s = 0.0f;
    if (rs >= 0) {
        const float* tb = tbl + rs * 3 * NB;
        float v0 = denorm(fa), v1 = denorm(fb), v2 = denorm(fc);
        int i0 = min(floor_pos(v0), 255);
        int i1 = min(floor_pos(v1), 255);
        int i2 = min(floor_pos(v2), 255);
        s = fabsf(v0 - tb[i0]) + fabsf(v1 - tb[NB + i1]) + fabsf(v2 - tb[2 * NB + i2]);
    }
    return s;
}

__global__ void __launch_bounds__(256) loss_kernel(
    const float4* __restrict__ fake, const int4* __restrict__ ma)
{
    __shared__ float tbl[12 * NB];
    __shared__ float wsum[8];
    for (int i = threadIdx.x; i < 12 * NB; i += 256) tbl[i] = g_tables[i];
    __syncthreads();

    float acc = 0.0f;
    int stride = gridDim.x * 256;
    for (int q = blockIdx.x * 256 + threadIdx.x; q < NQ; q += stride) {
        int4   a4 = ma[q];
        float4 f0 = fake[q], f1 = fake[q + NQ], f2 = fake[q + 2 * NQ];
        acc += loss_px(a4.x, f0.x, f1.x, f2.x, tbl);
        acc += loss_px(a4.y, f0.y, f1.y, f2.y, tbl);
        acc += loss_px(a4.z, f0.z, f1.z, f2.z, tbl);
        acc += loss_px(a4.w, f0.w, f1.w, f2.w, tbl);
    }

    // block reduction -> one double atomic per block
    #pragma unroll
    for (int off = 16; off > 0; off >>= 1)
        acc += __shfl_down_sync(0xffffffffu, acc, off);
    int lane = threadIdx.x & 31, wid = threadIdx.x >> 5;
    if (lane == 0) wsum[wid] = acc;
    __syncthreads();
    if (threadIdx.x == 0) {
        float s = 0.0f;
        #pragma unroll
        for (int i = 0; i < 8; i++) s += wsum[i];
        atomicAdd(&g_acc, (double)s);
    }
}

// ---------------------------------------------------------------- K4: finalize
__global__ void final_kernel(float* out) {
    // loss = 0.1 * total_abs_sum / (3*H*W); all four lambdas are 0.1
    out[0] = (float)(g_acc * (0.1 / 12582912.0));
}

// ---------------------------------------------------------------- launch
extern "C" void kernel_launch(void* const* d_in, const int* in_sizes, int n_in,
                              void* d_out, int out_size)
{
    (void)in_sizes; (void)n_in; (void)out_size;
    const float4* fake = (const float4*)d_in[0];
    const float4* refb = (const float4*)d_in[1];
    const int4*   ma   = (const int4*)d_in[2];
    const int4*   mb   = (const int4*)d_in[3];
    float* out = (float*)d_out;

    zero_kernel <<<24, 256>>>();
    hist_kernel <<<296, 512>>>(fake, refb, ma, mb);
    table_kernel<<<12, 256>>>();
    loss_kernel <<<592, 256>>>(fake, ma);
    final_kernel<<<1, 1>>>(out);
}